// round 16
// baseline (speedup 1.0000x reference)
#include <cuda_runtime.h>
#include <cuda_fp16.h>
#include <cstdint>

#define BB     2048
#define TT     2049
#define SS     2048      // T-1
#define KK     8
#define NTH    1024      // threads per CTA
#define NW     32        // warps per CTA
#define WT     64        // timesteps per warp
#define NCH    4         // chunks per warp
#define CHT    16        // timesteps per chunk (2 lanes per t)
#define GRID   152       // persistent CTAs (GB300: 152 SMs; robust to fewer via stealing)
#define GAMMA_F 0.99f

// smem (floats): b0A,b0M,b1A,b1M [NW*KK each] | red [NW]
#define SMEM_BYTES ((4*NW*KK + NW)*4)

__device__ unsigned int g_row_counter;

__global__ __launch_bounds__(NTH, 1)
void retrace_loss_kernel(const float* __restrict__ q,
                         const float* __restrict__ tq,
                         const float* __restrict__ tv,
                         const float* __restrict__ rw,
                         const float* __restrict__ olp,
                         const float* __restrict__ tlp,
                         float* __restrict__ out)
{
    extern __shared__ char smem[];
    float* b0A  = (float*)smem;            // NW*KK
    float* b0M  = b0A + NW * KK;
    float* b1A  = b0M + NW * KK;
    float* b1M  = b1A + NW * KK;
    float* red  = b1M + NW * KK;           // NW
    __shared__ unsigned int s_row;

    const int tid  = threadIdx.x;
    const int lane = tid & 31;
    const int w    = tid >> 5;       // warp 0..31, owns t [w*64, w*64+64)
    const int sl   = lane >> 1;      // timestep within chunk 0..15
    const int kg   = lane & 1;       // k-group (floats [kg*4, kg*4+4))
    const unsigned fullm = 0xFFFFFFFFu;

    float lsum = 0.0f;               // accumulated across all rows this thread touches

    for (;;) {
        if (tid == 0) s_row = atomicAdd(&g_row_counter, 1u);
        __syncthreads();
        const unsigned row = s_row;
        if (row >= BB) break;

        const size_t base3 = (size_t)row * TT * KK;
        const size_t base2 = (size_t)row * TT;

        // register-resident per-element state (relative to warp-region end)
        float4 As_reg[NCH];    // Asuf
        uint2  ms_reg[NCH];    // Msuf as 2x half2

        float4 Ar = make_float4(0.f, 0.f, 0.f, 0.f);
        float4 Mr = make_float4(1.f, 1.f, 1.f, 1.f);

        #pragma unroll
        for (int ch = NCH - 1; ch >= 0; --ch) {
            const int t = w * WT + ch * CHT + sl;
            const size_t o0 = base3 + (size_t)t * KK + kg * 4;

            // fully coalesced streaming loads (no q in phase 1)
            const float4 r4 = __ldcs((const float4*)(rw  + o0));
            const float4 v4 = __ldcs((const float4*)(tv  + o0 + KK));
            const float4 Q4 = __ldcs((const float4*)(tq  + o0 + KK));
            const float4 l4 = __ldcs((const float4*)(tlp + o0 + KK));
            const float  ol = olp[base2 + t + 1];

            const bool last = (t == SS - 1);
            const float sgn = last ? 1.0f : -1.0f;
            const float gm  = last ? 0.0f : GAMMA_F;

            float4 A, M;
            { float c = __expf(fminf(l4.x - ol, 0.f));
              A.x = fmaf(GAMMA_F, fmaf(sgn * c, Q4.x, v4.x), r4.x); M.x = gm * c; }
            { float c = __expf(fminf(l4.y - ol, 0.f));
              A.y = fmaf(GAMMA_F, fmaf(sgn * c, Q4.y, v4.y), r4.y); M.y = gm * c; }
            { float c = __expf(fminf(l4.z - ol, 0.f));
              A.z = fmaf(GAMMA_F, fmaf(sgn * c, Q4.z, v4.z), r4.z); M.z = gm * c; }
            { float c = __expf(fminf(l4.w - ol, 0.f));
              A.w = fmaf(GAMMA_F, fmaf(sgn * c, Q4.w, v4.w), r4.w); M.w = gm * c; }

            // warp suffix scan over 16 timesteps (lanes)
            #pragma unroll
            for (int d = 1; d < 16; d <<= 1) {
                float4 Ao, Mo;
                Ao.x = __shfl_down_sync(fullm, A.x, 2 * d);
                Ao.y = __shfl_down_sync(fullm, A.y, 2 * d);
                Ao.z = __shfl_down_sync(fullm, A.z, 2 * d);
                Ao.w = __shfl_down_sync(fullm, A.w, 2 * d);
                Mo.x = __shfl_down_sync(fullm, M.x, 2 * d);
                Mo.y = __shfl_down_sync(fullm, M.y, 2 * d);
                Mo.z = __shfl_down_sync(fullm, M.z, 2 * d);
                Mo.w = __shfl_down_sync(fullm, M.w, 2 * d);
                if (sl + d < 16) {
                    A.x = fmaf(M.x, Ao.x, A.x); M.x *= Mo.x;
                    A.y = fmaf(M.y, Ao.y, A.y); M.y *= Mo.y;
                    A.z = fmaf(M.z, Ao.z, A.z); M.z *= Mo.z;
                    A.w = fmaf(M.w, Ao.w, A.w); M.w *= Mo.w;
                }
            }

            // full-chunk transform lives in lanes 0/1
            float4 Af, Mf;
            Af.x = __shfl_sync(fullm, A.x, kg);
            Af.y = __shfl_sync(fullm, A.y, kg);
            Af.z = __shfl_sync(fullm, A.z, kg);
            Af.w = __shfl_sync(fullm, A.w, kg);
            Mf.x = __shfl_sync(fullm, M.x, kg);
            Mf.y = __shfl_sync(fullm, M.y, kg);
            Mf.z = __shfl_sync(fullm, M.z, kg);
            Mf.w = __shfl_sync(fullm, M.w, kg);

            // suffix relative to warp-region end
            float4 As, Ms;
            As.x = fmaf(M.x, Ar.x, A.x);  Ms.x = M.x * Mr.x;
            As.y = fmaf(M.y, Ar.y, A.y);  Ms.y = M.y * Mr.y;
            As.z = fmaf(M.z, Ar.z, A.z);  Ms.z = M.z * Mr.z;
            As.w = fmaf(M.w, Ar.w, A.w);  Ms.w = M.w * Mr.w;

            As_reg[ch] = As;
            __half2 h01 = __floats2half2_rn(Ms.x, Ms.y);
            __half2 h23 = __floats2half2_rn(Ms.z, Ms.w);
            ms_reg[ch].x = *(uint32_t*)&h01;
            ms_reg[ch].y = *(uint32_t*)&h23;

            Ar.x = fmaf(Mf.x, Ar.x, Af.x);  Mr.x *= Mf.x;
            Ar.y = fmaf(Mf.y, Ar.y, Af.y);  Mr.y *= Mf.y;
            Ar.z = fmaf(Mf.z, Ar.z, Af.z);  Mr.z *= Mf.z;
            Ar.w = fmaf(Mf.w, Ar.w, Af.w);  Mr.w *= Mf.w;
        }

        // warp totals -> smem buffer 0
        if (lane < 2) {
            *(float4*)(b0A + w * KK + kg * 4) = Ar;
            *(float4*)(b0M + w * KK + kg * 4) = Mr;
        }
        __syncthreads();

        // issue q loads NOW: they fly during the smem scan
        float4 q_reg[NCH];
        #pragma unroll
        for (int ch = 0; ch < NCH; ++ch) {
            const int t = w * WT + ch * CHT + sl;
            const size_t o0 = base3 + (size_t)t * KK + kg * 4;
            q_reg[ch] = __ldcs((const float4*)(q + o0));
        }

        // cooperative suffix scan over warp totals: S_w = T_w ∘ ... ∘ T_31
        #define SCAN_ROUND(SA, SM, DA, DM, D)                                 \
        do {                                                                  \
            if (tid < NW * KK) {                                              \
                const int ww = tid >> 3;                                      \
                float a = SA[tid], m = SM[tid];                               \
                if (ww + (D) < NW) {                                          \
                    a = fmaf(m, SA[tid + (D) * KK], a);                       \
                    m *= SM[tid + (D) * KK];                                  \
                }                                                             \
                DA[tid] = a; DM[tid] = m;                                     \
            }                                                                 \
            __syncthreads();                                                  \
        } while (0)

        SCAN_ROUND(b0A, b0M, b1A, b1M, 1);
        SCAN_ROUND(b1A, b1M, b0A, b0M, 2);
        SCAN_ROUND(b0A, b0M, b1A, b1M, 4);
        SCAN_ROUND(b1A, b1M, b0A, b0M, 8);
        SCAN_ROUND(b0A, b0M, b1A, b1M, 16);
        // inclusive suffix S_w now in b1A/b1M

        // carry at end of this warp's region (seed 0: CTA covers full row)
        float4 x4;
        if (w < NW - 1) {
            x4 = *(const float4*)(b1A + (w + 1) * KK + kg * 4);
        } else {
            x4 = make_float4(0.f, 0.f, 0.f, 0.f);
        }

        // Phase 2: d = q - (Asuf + Msuf * x4)
        #pragma unroll
        for (int ch = 0; ch < NCH; ++ch) {
            const float4 a4 = As_reg[ch];
            const float4 q4 = q_reg[ch];
            const float2 m01 = __half22float2(*(const __half2*)&ms_reg[ch].x);
            const float2 m23 = __half22float2(*(const __half2*)&ms_reg[ch].y);

            float d, ad;
            d = q4.x - fmaf(m01.x, x4.x, a4.x); ad = fabsf(d);
            lsum += (ad < 1.0f) ? 0.5f * d * d : (ad - 0.5f);
            d = q4.y - fmaf(m01.y, x4.y, a4.y); ad = fabsf(d);
            lsum += (ad < 1.0f) ? 0.5f * d * d : (ad - 0.5f);
            d = q4.z - fmaf(m23.x, x4.z, a4.z); ad = fabsf(d);
            lsum += (ad < 1.0f) ? 0.5f * d * d : (ad - 0.5f);
            d = q4.w - fmaf(m23.y, x4.w, a4.w); ad = fabsf(d);
            lsum += (ad < 1.0f) ? 0.5f * d * d : (ad - 0.5f);
        }
        // no trailing sync needed: loop-top __syncthreads protects s_row/smem reuse
    }

    // final reduce + atomic (once per CTA)
    #pragma unroll
    for (int off = 16; off > 0; off >>= 1)
        lsum += __shfl_down_sync(fullm, lsum, off);
    if (lane == 0) red[w] = lsum;
    __syncthreads();
    if (tid < 32) {
        float v = red[tid];
        #pragma unroll
        for (int off = 16; off > 0; off >>= 1)
            v += __shfl_down_sync(fullm, v, off);
        if (tid == 0)
            atomicAdd(out, v * (1.0f / 33554432.0f));   // mean over 2048*2048*8
    }
}

extern "C" void kernel_launch(void* const* d_in, const int* in_sizes, int n_in,
                              void* d_out, int out_size)
{
    (void)in_sizes; (void)n_in; (void)out_size;
    const float* q   = (const float*)d_in[0];
    const float* tq  = (const float*)d_in[1];
    const float* tv  = (const float*)d_in[2];
    const float* rw  = (const float*)d_in[3];
    const float* olp = (const float*)d_in[4];
    const float* tlp = (const float*)d_in[5];
    float* out = (float*)d_out;

    cudaFuncSetAttribute(retrace_loss_kernel,
                         cudaFuncAttributeMaxDynamicSharedMemorySize,
                         SMEM_BYTES);

    // reset row counter + output accumulator (graph-capturable, no allocation)
    void* ctr_addr = nullptr;
    cudaGetSymbolAddress(&ctr_addr, g_row_counter);
    cudaMemsetAsync(ctr_addr, 0, sizeof(unsigned int));
    cudaMemsetAsync(out, 0, sizeof(float));

    retrace_loss_kernel<<<GRID, NTH, SMEM_BYTES>>>(q, tq, tv, rw, olp, tlp, out);
}

// round 17
// speedup vs baseline: 1.0193x; 1.0193x over previous
#include <cuda_runtime.h>
#include <cuda_fp16.h>
#include <cstdint>

#define BB     2048
#define TT     2049
#define SS     2048      // T-1
#define KK     8
#define NTH    1024      // threads per CTA
#define NW     32        // warps per CTA
#define WT     64        // timesteps per warp
#define NCH    4         // chunks per warp
#define CHT    16        // timesteps per chunk (2 lanes per t)
#define GRID   152       // persistent CTAs (GB300: 152 SMs)
#define GAMMA_F 0.99f

// smem (floats): b0A,b0M [NW*KK each] | b1A [NW*KK] | red [NW]
#define SMEM_BYTES ((3*NW*KK + NW)*4)

__device__ unsigned int g_row_counter;

__global__ __launch_bounds__(NTH, 1)
void retrace_loss_kernel(const float* __restrict__ q,
                         const float* __restrict__ tq,
                         const float* __restrict__ tv,
                         const float* __restrict__ rw,
                         const float* __restrict__ olp,
                         const float* __restrict__ tlp,
                         float* __restrict__ out)
{
    extern __shared__ char smem[];
    float* b0A  = (float*)smem;            // NW*KK   warp-total A
    float* b0M  = b0A + NW * KK;           // NW*KK   warp-total M
    float* b1A  = b0M + NW * KK;           // NW*KK   inclusive suffix A
    float* red  = b1A + NW * KK;           // NW
    __shared__ unsigned int s_row;

    const int tid  = threadIdx.x;
    const int lane = tid & 31;
    const int w    = tid >> 5;       // warp 0..31, owns t [w*64, w*64+64)
    const int sl   = lane >> 1;      // timestep within chunk 0..15
    const int kg   = lane & 1;       // k-group (floats [kg*4, kg*4+4))
    const unsigned fullm = 0xFFFFFFFFu;

    float lsum = 0.0f;

    // first row grab
    if (tid == 0) s_row = atomicAdd(&g_row_counter, 1u);
    __syncthreads();
    unsigned row = s_row;

    while (row < BB) {
        const size_t base3 = (size_t)row * TT * KK;
        const size_t base2 = (size_t)row * TT;

        // register-resident per-element state (relative to warp-region end)
        float4 As_reg[NCH];    // Asuf
        uint2  ms_reg[NCH];    // Msuf as 2x half2

        float4 Ar = make_float4(0.f, 0.f, 0.f, 0.f);
        float4 Mr = make_float4(1.f, 1.f, 1.f, 1.f);

        #pragma unroll
        for (int ch = NCH - 1; ch >= 0; --ch) {
            const int t = w * WT + ch * CHT + sl;
            const size_t o0 = base3 + (size_t)t * KK + kg * 4;

            const float4 r4 = __ldcs((const float4*)(rw  + o0));
            const float4 v4 = __ldcs((const float4*)(tv  + o0 + KK));
            const float4 Q4 = __ldcs((const float4*)(tq  + o0 + KK));
            const float4 l4 = __ldcs((const float4*)(tlp + o0 + KK));
            const float  ol = olp[base2 + t + 1];

            const bool last = (t == SS - 1);
            const float sgn = last ? 1.0f : -1.0f;
            const float gm  = last ? 0.0f : GAMMA_F;

            float4 A, M;
            { float c = __expf(fminf(l4.x - ol, 0.f));
              A.x = fmaf(GAMMA_F, fmaf(sgn * c, Q4.x, v4.x), r4.x); M.x = gm * c; }
            { float c = __expf(fminf(l4.y - ol, 0.f));
              A.y = fmaf(GAMMA_F, fmaf(sgn * c, Q4.y, v4.y), r4.y); M.y = gm * c; }
            { float c = __expf(fminf(l4.z - ol, 0.f));
              A.z = fmaf(GAMMA_F, fmaf(sgn * c, Q4.z, v4.z), r4.z); M.z = gm * c; }
            { float c = __expf(fminf(l4.w - ol, 0.f));
              A.w = fmaf(GAMMA_F, fmaf(sgn * c, Q4.w, v4.w), r4.w); M.w = gm * c; }

            // warp suffix scan over 16 timesteps (lanes)
            #pragma unroll
            for (int d = 1; d < 16; d <<= 1) {
                float4 Ao, Mo;
                Ao.x = __shfl_down_sync(fullm, A.x, 2 * d);
                Ao.y = __shfl_down_sync(fullm, A.y, 2 * d);
                Ao.z = __shfl_down_sync(fullm, A.z, 2 * d);
                Ao.w = __shfl_down_sync(fullm, A.w, 2 * d);
                Mo.x = __shfl_down_sync(fullm, M.x, 2 * d);
                Mo.y = __shfl_down_sync(fullm, M.y, 2 * d);
                Mo.z = __shfl_down_sync(fullm, M.z, 2 * d);
                Mo.w = __shfl_down_sync(fullm, M.w, 2 * d);
                if (sl + d < 16) {
                    A.x = fmaf(M.x, Ao.x, A.x); M.x *= Mo.x;
                    A.y = fmaf(M.y, Ao.y, A.y); M.y *= Mo.y;
                    A.z = fmaf(M.z, Ao.z, A.z); M.z *= Mo.z;
                    A.w = fmaf(M.w, Ao.w, A.w); M.w *= Mo.w;
                }
            }

            // full-chunk transform lives in lanes 0/1
            float4 Af, Mf;
            Af.x = __shfl_sync(fullm, A.x, kg);
            Af.y = __shfl_sync(fullm, A.y, kg);
            Af.z = __shfl_sync(fullm, A.z, kg);
            Af.w = __shfl_sync(fullm, A.w, kg);
            Mf.x = __shfl_sync(fullm, M.x, kg);
            Mf.y = __shfl_sync(fullm, M.y, kg);
            Mf.z = __shfl_sync(fullm, M.z, kg);
            Mf.w = __shfl_sync(fullm, M.w, kg);

            // suffix relative to warp-region end
            float4 As, Ms;
            As.x = fmaf(M.x, Ar.x, A.x);  Ms.x = M.x * Mr.x;
            As.y = fmaf(M.y, Ar.y, A.y);  Ms.y = M.y * Mr.y;
            As.z = fmaf(M.z, Ar.z, A.z);  Ms.z = M.z * Mr.z;
            As.w = fmaf(M.w, Ar.w, A.w);  Ms.w = M.w * Mr.w;

            As_reg[ch] = As;
            __half2 h01 = __floats2half2_rn(Ms.x, Ms.y);
            __half2 h23 = __floats2half2_rn(Ms.z, Ms.w);
            ms_reg[ch].x = *(uint32_t*)&h01;
            ms_reg[ch].y = *(uint32_t*)&h23;

            Ar.x = fmaf(Mf.x, Ar.x, Af.x);  Mr.x *= Mf.x;
            Ar.y = fmaf(Mf.y, Ar.y, Af.y);  Mr.y *= Mf.y;
            Ar.z = fmaf(Mf.z, Ar.z, Af.z);  Mr.z *= Mf.z;
            Ar.w = fmaf(Mf.w, Ar.w, Af.w);  Mr.w *= Mf.w;
        }

        // warp totals -> smem
        if (lane < 2) {
            *(float4*)(b0A + w * KK + kg * 4) = Ar;
            *(float4*)(b0M + w * KK + kg * 4) = Mr;
        }
        __syncthreads();                       // sync1: totals visible

        // prefetch next row id: atomic latency overlaps the scan below
        if (tid == 0) s_row = atomicAdd(&g_row_counter, 1u);

        if (w == 0) {
            // single-warp register suffix scan over 32 warp-totals.
            // lane = source warp index; 8 k-values per lane in registers.
            const int base = lane * KK;
            float4 A0 = *(const float4*)(b0A + base);
            float4 A1 = *(const float4*)(b0A + base + 4);
            float4 M0 = *(const float4*)(b0M + base);
            float4 M1 = *(const float4*)(b0M + base + 4);
            #pragma unroll
            for (int d = 1; d < 32; d <<= 1) {
                float4 Ao0, Ao1, Mo0, Mo1;
                Ao0.x = __shfl_down_sync(fullm, A0.x, d);
                Ao0.y = __shfl_down_sync(fullm, A0.y, d);
                Ao0.z = __shfl_down_sync(fullm, A0.z, d);
                Ao0.w = __shfl_down_sync(fullm, A0.w, d);
                Ao1.x = __shfl_down_sync(fullm, A1.x, d);
                Ao1.y = __shfl_down_sync(fullm, A1.y, d);
                Ao1.z = __shfl_down_sync(fullm, A1.z, d);
                Ao1.w = __shfl_down_sync(fullm, A1.w, d);
                Mo0.x = __shfl_down_sync(fullm, M0.x, d);
                Mo0.y = __shfl_down_sync(fullm, M0.y, d);
                Mo0.z = __shfl_down_sync(fullm, M0.z, d);
                Mo0.w = __shfl_down_sync(fullm, M0.w, d);
                Mo1.x = __shfl_down_sync(fullm, M1.x, d);
                Mo1.y = __shfl_down_sync(fullm, M1.y, d);
                Mo1.z = __shfl_down_sync(fullm, M1.z, d);
                Mo1.w = __shfl_down_sync(fullm, M1.w, d);
                if (lane + d < 32) {
                    A0.x = fmaf(M0.x, Ao0.x, A0.x); M0.x *= Mo0.x;
                    A0.y = fmaf(M0.y, Ao0.y, A0.y); M0.y *= Mo0.y;
                    A0.z = fmaf(M0.z, Ao0.z, A0.z); M0.z *= Mo0.z;
                    A0.w = fmaf(M0.w, Ao0.w, A0.w); M0.w *= Mo0.w;
                    A1.x = fmaf(M1.x, Ao1.x, A1.x); M1.x *= Mo1.x;
                    A1.y = fmaf(M1.y, Ao1.y, A1.y); M1.y *= Mo1.y;
                    A1.z = fmaf(M1.z, Ao1.z, A1.z); M1.z *= Mo1.z;
                    A1.w = fmaf(M1.w, Ao1.w, A1.w); M1.w *= Mo1.w;
                }
            }
            // only A of the inclusive suffix is needed downstream (seed = 0)
            *(float4*)(b1A + base)     = A0;
            *(float4*)(b1A + base + 4) = A1;
        }

        // q prefetch: warps 1..31 reach here immediately after sync1 and keep
        // DRAM busy while warp 0 runs the register scan.
        float4 q_reg[NCH];
        #pragma unroll
        for (int ch = 0; ch < NCH; ++ch) {
            const int t = w * WT + ch * CHT + sl;
            const size_t o0 = base3 + (size_t)t * KK + kg * 4;
            q_reg[ch] = __ldcs((const float4*)(q + o0));
        }

        __syncthreads();                       // sync2: publishes b1A and s_row

        // carry at end of this warp's region (seed 0: CTA covers full row)
        float4 x4;
        if (w < NW - 1) {
            x4 = *(const float4*)(b1A + (w + 1) * KK + kg * 4);
        } else {
            x4 = make_float4(0.f, 0.f, 0.f, 0.f);
        }
        const unsigned next_row = s_row;

        // Phase 2: d = q - (Asuf + Msuf * x4)
        #pragma unroll
        for (int ch = 0; ch < NCH; ++ch) {
            const float4 a4 = As_reg[ch];
            const float4 q4 = q_reg[ch];
            const float2 m01 = __half22float2(*(const __half2*)&ms_reg[ch].x);
            const float2 m23 = __half22float2(*(const __half2*)&ms_reg[ch].y);

            float d, ad;
            d = q4.x - fmaf(m01.x, x4.x, a4.x); ad = fabsf(d);
            lsum += (ad < 1.0f) ? 0.5f * d * d : (ad - 0.5f);
            d = q4.y - fmaf(m01.y, x4.y, a4.y); ad = fabsf(d);
            lsum += (ad < 1.0f) ? 0.5f * d * d : (ad - 0.5f);
            d = q4.z - fmaf(m23.x, x4.z, a4.z); ad = fabsf(d);
            lsum += (ad < 1.0f) ? 0.5f * d * d : (ad - 0.5f);
            d = q4.w - fmaf(m23.y, x4.w, a4.w); ad = fabsf(d);
            lsum += (ad < 1.0f) ? 0.5f * d * d : (ad - 0.5f);
        }

        row = next_row;
    }

    // final reduce + atomic (once per CTA)
    #pragma unroll
    for (int off = 16; off > 0; off >>= 1)
        lsum += __shfl_down_sync(fullm, lsum, off);
    if (lane == 0) red[w] = lsum;
    __syncthreads();
    if (tid < 32) {
        float v = red[tid];
        #pragma unroll
        for (int off = 16; off > 0; off >>= 1)
            v += __shfl_down_sync(fullm, v, off);
        if (tid == 0)
            atomicAdd(out, v * (1.0f / 33554432.0f));   // mean over 2048*2048*8
    }
}

extern "C" void kernel_launch(void* const* d_in, const int* in_sizes, int n_in,
                              void* d_out, int out_size)
{
    (void)in_sizes; (void)n_in; (void)out_size;
    const float* q   = (const float*)d_in[0];
    const float* tq  = (const float*)d_in[1];
    const float* tv  = (const float*)d_in[2];
    const float* rw  = (const float*)d_in[3];
    const float* olp = (const float*)d_in[4];
    const float* tlp = (const float*)d_in[5];
    float* out = (float*)d_out;

    cudaFuncSetAttribute(retrace_loss_kernel,
                         cudaFuncAttributeMaxDynamicSharedMemorySize,
                         SMEM_BYTES);

    // reset row counter + output accumulator (graph-capturable, no allocation)
    void* ctr_addr = nullptr;
    cudaGetSymbolAddress(&ctr_addr, g_row_counter);
    cudaMemsetAsync(ctr_addr, 0, sizeof(unsigned int));
    cudaMemsetAsync(out, 0, sizeof(float));

    retrace_loss_kernel<<<GRID, NTH, SMEM_BYTES>>>(q, tq, tv, rw, olp, tlp, out);
}